// round 4
// baseline (speedup 1.0000x reference)
#include <cuda_runtime.h>
#include <math.h>

#define NN 32
#define CC 64
#define TT 512
#define VV 25
#define C4V 16
#define W3V 75
#define COV 64
#define KSPLIT 8
#define KTOT (C4V*TT)        /* 8192 */
#define KCHUNK (KTOT/KSPLIT) /* 1024 */
#define TVTOT (TT*VV)        /* 12800 */

typedef unsigned long long ull;

__device__ __forceinline__ ull pk2(float lo, float hi) {
    ull r; asm("mov.b64 %0, {%1,%2};" : "=l"(r) : "f"(lo), "f"(hi)); return r;
}
__device__ __forceinline__ ull fma2(ull a, ull b, ull c) {
    ull d; asm("fma.rn.f32x2 %0, %1, %2, %3;" : "=l"(d) : "l"(a), "l"(b), "l"(c)); return d;
}
__device__ __forceinline__ void unpk2(ull v, float& lo, float& hi) {
    asm("mov.b64 {%0,%1}, %2;" : "=f"(lo), "=f"(hi) : "l"(v));
}

// -------- device scratch --------
__device__ float g_B[NN*C4V*TT*VV];          // conv_a(x), ch-major, NO bias
__device__ float g_L[(size_t)NN*TVTOT*64];   // [n][tv][ch]  ch=[d 0-15|g0|g1|g2], WITH bias
__device__ float g_Gpart[NN*KSPLIT*W3V*W3V];
__device__ float g_att[NN*W3V*W3V];

// ============================================================
// K1: 80-channel 1x1 conv GEMM on raw x (conv commutes with unfold)
// ============================================================
#define K1_TV 128
__global__ void __launch_bounds__(320) k1_conv80(
    const float* __restrict__ x,
    const float* __restrict__ Wa,
    const float* __restrict__ Wd, const float* __restrict__ bd,
    const float* __restrict__ Wc, const float* __restrict__ bc)
{
    extern __shared__ float sm[];
    float* sX = sm;                 // [64][128]
    float* sW = sm + 8192;          // [64c][80j]
    float* sB = sm + 8192 + 5120;   // [80]
    int tid = threadIdx.x;
    int n   = blockIdx.y;
    int tv0 = blockIdx.x * K1_TV;

    for (int i = tid; i < 5120; i += 320) {
        int c = i / 80, j = i - c*80;
        float w;
        if (j < 16)      w = Wd[j*CC + c];
        else if (j < 64) w = Wc[(j-16)*CC + c];
        else             w = Wa[(j-64)*CC + c];
        sW[i] = w;
    }
    if (tid < 80) sB[tid] = (tid < 16) ? bd[tid] : (tid < 64 ? bc[tid-16] : 0.f);

    const float* xp = x + (size_t)n*CC*TVTOT + tv0;
    for (int i = tid; i < 2048; i += 320) {
        int c = i >> 5, o = (i & 31) << 2;
        *reinterpret_cast<float4*>(&sX[c*128 + o]) =
            *reinterpret_cast<const float4*>(xp + (size_t)c*TVTOT + o);
    }
    __syncthreads();

    int jt = tid / 32;             // 0..9 (8 channels each)
    int tq = (tid & 31) << 2;      // local tv, 4 wide
    ull acc2[8][2];
#pragma unroll
    for (int a = 0; a < 8; a++) { acc2[a][0] = 0ull; acc2[a][1] = 0ull; }

#pragma unroll 4
    for (int c = 0; c < 64; c++) {
        ulonglong2 xv = *reinterpret_cast<const ulonglong2*>(&sX[c*128 + tq]);
        float4 wa = *reinterpret_cast<const float4*>(&sW[c*80 + jt*8]);
        float4 wb = *reinterpret_cast<const float4*>(&sW[c*80 + jt*8 + 4]);
        ull pw[8];
        pw[0]=pk2(wa.x,wa.x); pw[1]=pk2(wa.y,wa.y); pw[2]=pk2(wa.z,wa.z); pw[3]=pk2(wa.w,wa.w);
        pw[4]=pk2(wb.x,wb.x); pw[5]=pk2(wb.y,wb.y); pw[6]=pk2(wb.z,wb.z); pw[7]=pk2(wb.w,wb.w);
#pragma unroll
        for (int jj = 0; jj < 8; jj++) {
            acc2[jj][0] = fma2(pw[jj], xv.x, acc2[jj][0]);
            acc2[jj][1] = fma2(pw[jj], xv.y, acc2[jj][1]);
        }
    }

    float acc[8][4];
#pragma unroll
    for (int jj = 0; jj < 8; jj++) {
        unpk2(acc2[jj][0], acc[jj][0], acc[jj][1]);
        unpk2(acc2[jj][1], acc[jj][2], acc[jj][3]);
    }

    int j0 = jt*8;
    if (j0 < 64) {
        float b[8];
#pragma unroll
        for (int jj = 0; jj < 8; jj++) b[jj] = sB[j0+jj];
        float* gl = g_L + ((size_t)n*TVTOT + tv0 + tq)*64 + j0;
#pragma unroll
        for (int t4 = 0; t4 < 4; t4++) {
            float4 r0 = make_float4(acc[0][t4]+b[0], acc[1][t4]+b[1],
                                    acc[2][t4]+b[2], acc[3][t4]+b[3]);
            float4 r1 = make_float4(acc[4][t4]+b[4], acc[5][t4]+b[5],
                                    acc[6][t4]+b[6], acc[7][t4]+b[7]);
            *reinterpret_cast<float4*>(gl + (size_t)t4*64)     = r0;
            *reinterpret_cast<float4*>(gl + (size_t)t4*64 + 4) = r1;
        }
    } else {
#pragma unroll
        for (int jj = 0; jj < 8; jj++) {
            int o = j0 - 64 + jj;
            float4 r = make_float4(acc[jj][0], acc[jj][1], acc[jj][2], acc[jj][3]);
            *reinterpret_cast<float4*>(g_B + (size_t)(n*C4V + o)*TVTOT + tv0 + tq) = r;
        }
    }
}

// ============================================================
// K2: Gram partials (unchanged)
// ============================================================
__global__ void k2_gram(const float* __restrict__ ba)
{
    __shared__ float tile[32][W3V + 1];
    int n  = blockIdx.y;
    int ks = blockIdx.x;
    int tid = threadIdx.x;
    int tw1 = tid / 15, tw2 = tid % 15;

    float acc[5][5];
#pragma unroll
    for (int i = 0; i < 5; i++)
#pragma unroll
        for (int j = 0; j < 5; j++) acc[i][j] = 0.f;

    int k0 = ks * KCHUNK;
    for (int kt = 0; kt < KCHUNK; kt += 32) {
        for (int i = tid; i < 32*W3V; i += blockDim.x) {
            int r = i / W3V, w = i - r*W3V;
            int k = k0 + kt + r;
            int o = k >> 9, t = k & 511;
            int win = w / VV, v = w - win*VV;
            int ts = t + win - 1;
            float val = ba[o];
            if (ts >= 0 && ts < TT)
                val += g_B[((size_t)(n*C4V + o)*TT + ts)*VV + v];
            tile[r][w] = val;
        }
        __syncthreads();
        if (tid < 225) {
#pragma unroll 4
            for (int r = 0; r < 32; r++) {
                float av[5], bv[5];
#pragma unroll
                for (int i = 0; i < 5; i++) { av[i] = tile[r][tw1*5+i]; bv[i] = tile[r][tw2*5+i]; }
#pragma unroll
                for (int i = 0; i < 5; i++)
#pragma unroll
                    for (int j = 0; j < 5; j++) acc[i][j] += av[i]*bv[j];
            }
        }
        __syncthreads();
    }
    if (tid < 225) {
        float* gp = g_Gpart + (size_t)(n*KSPLIT + ks)*W3V*W3V;
#pragma unroll
        for (int i = 0; i < 5; i++)
#pragma unroll
            for (int j = 0; j < 5; j++)
                gp[(tw1*5+i)*W3V + (tw2*5+j)] = acc[i][j];
    }
}

// ============================================================
// K3: reduce + softmax over w1 (unchanged)
// ============================================================
__global__ void k3_softmax()
{
    __shared__ float sG[W3V*W3V];
    int n = blockIdx.x, tid = threadIdx.x;
    for (int i = tid; i < W3V*W3V; i += blockDim.x) {
        float s = 0.f;
        for (int p = 0; p < KSPLIT; p++)
            s += g_Gpart[(size_t)(n*KSPLIT + p)*W3V*W3V + i];
        sG[i] = s * (1.0f / (float)W3V);
    }
    __syncthreads();
    if (tid < W3V) {
        float mx = -1e30f;
        for (int w1 = 0; w1 < W3V; w1++) mx = fmaxf(mx, sG[w1*W3V + tid]);
        float sum = 0.f;
        for (int w1 = 0; w1 < W3V; w1++) {
            float e = expf(sG[w1*W3V + tid] - mx);
            sG[w1*W3V + tid] = e;
            sum += e;
        }
        float inv = 1.f / sum;
        for (int w1 = 0; w1 < W3V; w1++)
            g_att[(size_t)n*W3V*W3V + w1*W3V + tid] = sG[w1*W3V + tid] * inv;
    }
}

// ============================================================
// K4 v4: per (n, 16 t).  X1[256][75] = sum of 4 chunks LT^T x R,
// f32x2 packed FMA, 4m x 10n register tiles.
// SMEM float offsets:
// ============================================================
#define SM_R    0       /* R chunk [75][80 stride] = 6000 */
#define SM_LTX  6000    /* LT [75][256] (19200) / X1 [256][75] union */
#define SM_WOT  25200   /* WoT [48][64] = 3072 */
#define SM_BN   28272   /* 128 */
#define SM_BIAS 28400   /* 64 */
#define SM_TOT  28464   /* floats = 113856 B */

__global__ void __launch_bounds__(512, 2) k4_main(
    const float* __restrict__ x,
    const float* __restrict__ A,   const float* __restrict__ PA,
    const float* __restrict__ bd,  const float* __restrict__ bc,
    const float* __restrict__ Wo,  const float* __restrict__ bo,
    const float* __restrict__ gma, const float* __restrict__ bta,
    const float* __restrict__ mean,const float* __restrict__ var,
    float* __restrict__ out)
{
    extern __shared__ float sm[];
    int tid = threadIdx.x;
    int n  = blockIdx.x >> 5;          // 32 blocks per n
    int t0 = (blockIdx.x & 31) << 4;   // 16 t per block

    // once-per-block constants
    for (int i = tid; i < 3072; i += 512) {
        int kc = i >> 6, o = i & 63;
        sm[SM_WOT + i] = Wo[o*48 + kc];
    }
    if (tid < 64) {
        float sc = gma[tid] * rsqrtf(var[tid] + 1e-5f);
        sm[SM_BN + tid]      = sc;
        sm[SM_BN + 64 + tid] = (bo[tid] - mean[tid])*sc + bta[tid];
        sm[SM_BIAS + tid]    = (tid < 16) ? bd[tid] : bc[tid-16];
    }

    // P3 tile mapping: warp-internal 8mt x 4nt for smem broadcast dedup
    int w = tid >> 5, l = tid & 31;
    int mt = ((w >> 1) << 3) + (l >> 2);   // 0..63
    int nt = ((w & 1) << 2) + (l & 3);     // 0..7
    int m0 = mt << 2;                      // 0..252
    int n0 = nt * 10;                      // 0..70

    ull acc[4][5];
#pragma unroll
    for (int a = 0; a < 4; a++)
#pragma unroll
        for (int j = 0; j < 5; j++) acc[a][j] = 0ull;

    const float* gl = g_L + (size_t)n*TVTOT*64;

    for (int kk = 0; kk < 4; kk++) {
        __syncthreads();   // constants ready (kk=0) / previous compute done
        // R chunk [75 k][stride 80]
        if (kk == 0) {
            const float* ap = g_att + (size_t)n*5625;
            for (int i = tid; i < 5625; i += 512) {
                int k = i / 75, c = i - k*75;
                sm[SM_R + k*80 + c] = ap[i];
            }
        } else {
            const float* a0 = A  + (size_t)(kk-1)*5625;
            const float* p0 = PA + (size_t)(kk-1)*5625;
            for (int i = tid; i < 5625; i += 512) {
                int k = i / 75, c = i - k*75;
                sm[SM_R + k*80 + c] = a0[i] + p0[i];
            }
        }
        // LT gather: LT[k][m=(it*16+c)]  (padding rows -> bias)
        for (int i = tid; i < 4800; i += 512) {
            int seg = i >> 2, q = (i & 3) << 2;
            int k  = seg >> 4, it = seg & 15;
            int win = (k*41) >> 10;   // k/25 for k<75
            int v   = k - win*25;
            int ts  = t0 + it + win - 1;
            float4 val;
            if ((unsigned)ts < TT)
                val = *reinterpret_cast<const float4*>(gl + ((size_t)(ts*25 + v) << 6) + kk*16 + q);
            else
                val = *reinterpret_cast<const float4*>(&sm[SM_BIAS + kk*16 + q]);
            *reinterpret_cast<float4*>(&sm[SM_LTX + k*256 + it*16 + q]) = val;
        }
        __syncthreads();

        // chunk GEMM: acc[4m][5 f32x2] += LT[k][m] * R[k][n-pair]
        const float* ltb = &sm[SM_LTX + m0];
#pragma unroll 3
        for (int k = 0; k < 75; k++) {
            float4 a4 = *reinterpret_cast<const float4*>(ltb + k*256);
            ull pa0 = pk2(a4.x, a4.x), pa1 = pk2(a4.y, a4.y);
            ull pa2 = pk2(a4.z, a4.z), pa3 = pk2(a4.w, a4.w);
            const ull* rp = reinterpret_cast<const ull*>(&sm[SM_R + k*80 + n0]);
#pragma unroll
            for (int j = 0; j < 5; j++) {
                ull r = rp[j];
                acc[0][j] = fma2(pa0, r, acc[0][j]);
                acc[1][j] = fma2(pa1, r, acc[1][j]);
                acc[2][j] = fma2(pa2, r, acc[2][j]);
                acc[3][j] = fma2(pa3, r, acc[3][j]);
            }
        }
    }
    __syncthreads();

    // X1 [m][75] overwrites LT region (n >= 75 lanes discarded)
#pragma unroll
    for (int mi = 0; mi < 4; mi++) {
        float* xb = &sm[SM_LTX + (m0 + mi)*75];
#pragma unroll
        for (int j = 0; j < 5; j++) {
            float lo, hi; unpk2(acc[mi][j], lo, hi);
            int nn = n0 + 2*j;
            if (nn < 75)     xb[nn]     = lo;
            if (nn + 1 < 75) xb[nn + 1] = hi;
        }
    }
    __syncthreads();

    // P4: out conv (1,3,1) + BN + residual + relu (two passes of 8 t)
    if (tid < 320) {
        int itb = tid / 40;
        int r   = tid - itb*40;
        int ot  = (r/5)*8, v0 = (r - (r/5)*5)*5;
#pragma unroll
        for (int pass = 0; pass < 2; pass++) {
            int it = itb + (pass << 3);
            float po[8][5];
#pragma unroll
            for (int a = 0; a < 8; a++)
#pragma unroll
                for (int b = 0; b < 5; b++) po[a][b] = 0.f;
            const float* x1b = &sm[SM_LTX + it*16*75];
#pragma unroll
            for (int c = 0; c < 16; c++) {
#pragma unroll
                for (int win = 0; win < 3; win++) {
                    int kc = c*3 + win;
                    float4 wA = *reinterpret_cast<const float4*>(&sm[SM_WOT + kc*64 + ot]);
                    float4 wB = *reinterpret_cast<const float4*>(&sm[SM_WOT + kc*64 + ot + 4]);
                    float wv[8] = {wA.x, wA.y, wA.z, wA.w, wB.x, wB.y, wB.z, wB.w};
                    float xv[5];
#pragma unroll
                    for (int i = 0; i < 5; i++) xv[i] = x1b[c*75 + win*25 + v0 + i];
#pragma unroll
                    for (int oo = 0; oo < 8; oo++)
#pragma unroll
                        for (int i = 0; i < 5; i++) po[oo][i] += wv[oo]*xv[i];
                }
            }
#pragma unroll
            for (int oo = 0; oo < 8; oo++) {
                int o = ot + oo;
                float sc = sm[SM_BN + o], sh = sm[SM_BN + 64 + o];
                size_t base = ((size_t)(n*COV + o)*TT + (t0 + it))*VV + v0;
#pragma unroll
                for (int i = 0; i < 5; i++)
                    out[base + i] = fmaxf(po[oo][i]*sc + sh + x[base + i], 0.f);
            }
        }
    }
}

// ============================================================
extern "C" void kernel_launch(void* const* d_in, const int* in_sizes, int n_in,
                              void* d_out, int out_size)
{
    (void)in_sizes; (void)n_in; (void)out_size;
    const float* x   = (const float*)d_in[0];
    const float* A   = (const float*)d_in[1];
    const float* PA  = (const float*)d_in[2];
    const float* Waw = (const float*)d_in[3];
    const float* Wab = (const float*)d_in[4];
    const float* Wdw = (const float*)d_in[5];
    const float* Wdb = (const float*)d_in[6];
    const float* Wcw = (const float*)d_in[7];
    const float* Wcb = (const float*)d_in[8];
    const float* Wow = (const float*)d_in[9];
    const float* Wob = (const float*)d_in[10];
    const float* gm  = (const float*)d_in[11];
    const float* bt  = (const float*)d_in[12];
    const float* mn  = (const float*)d_in[13];
    const float* vr  = (const float*)d_in[14];
    float* out = (float*)d_out;

    const size_t smem1 = (8192 + 5120 + 80) * sizeof(float);
    const size_t smem4 = SM_TOT * sizeof(float);
    cudaFuncSetAttribute(k1_conv80, cudaFuncAttributeMaxDynamicSharedMemorySize, (int)smem1);
    cudaFuncSetAttribute(k4_main,   cudaFuncAttributeMaxDynamicSharedMemorySize, (int)smem4);

    k1_conv80<<<dim3(TVTOT/K1_TV, NN), 320, smem1>>>(x, Waw, Wdw, Wdb, Wcw, Wcb);
    k2_gram  <<<dim3(KSPLIT, NN), 256>>>(Wab);
    k3_softmax<<<NN, 128>>>();
    k4_main  <<<NN*(TT/16), 512, smem4>>>(x, A, PA, Wdb, Wcb,
                                          Wow, Wob, gm, bt, mn, vr, out);
}

// round 5
// speedup vs baseline: 1.0533x; 1.0533x over previous
#include <cuda_runtime.h>
#include <math.h>

#define NN 32
#define CC 64
#define TT 512
#define VV 25
#define C4V 16
#define W3V 75
#define COV 64
#define KSPLIT 8
#define KTOT (C4V*TT)        /* 8192 */
#define KCHUNK (KTOT/KSPLIT) /* 1024 */
#define TVTOT (TT*VV)        /* 12800 */

typedef unsigned long long ull;

__device__ __forceinline__ ull pk2(float lo, float hi) {
    ull r; asm("mov.b64 %0, {%1,%2};" : "=l"(r) : "f"(lo), "f"(hi)); return r;
}
__device__ __forceinline__ ull fma2(ull a, ull b, ull c) {
    ull d; asm("fma.rn.f32x2 %0, %1, %2, %3;" : "=l"(d) : "l"(a), "l"(b), "l"(c)); return d;
}
__device__ __forceinline__ void unpk2(ull v, float& lo, float& hi) {
    asm("mov.b64 {%0,%1}, %2;" : "=f"(lo), "=f"(hi) : "l"(v));
}

// -------- device scratch --------
__device__ float g_B[NN*C4V*TT*VV];          // conv_a(x), ch-major, NO bias
__device__ float g_L[(size_t)NN*TVTOT*64];   // [n][tv][ch]  ch=[d 0-15|g0|g1|g2], WITH bias
__device__ float g_Gpart[NN*KSPLIT*W3V*W3V];
__device__ float g_att[NN*W3V*W3V];

// ============================================================
// K1: 80-channel 1x1 conv GEMM on raw x (conv commutes with unfold)
// ============================================================
#define K1_TV 128
__global__ void __launch_bounds__(320) k1_conv80(
    const float* __restrict__ x,
    const float* __restrict__ Wa,
    const float* __restrict__ Wd, const float* __restrict__ bd,
    const float* __restrict__ Wc, const float* __restrict__ bc)
{
    extern __shared__ float sm[];
    float* sX = sm;                 // [64][128]
    float* sW = sm + 8192;          // [64c][80j]
    float* sB = sm + 8192 + 5120;   // [80]
    int tid = threadIdx.x;
    int n   = blockIdx.y;
    int tv0 = blockIdx.x * K1_TV;

    for (int i = tid; i < 5120; i += 320) {
        int c = i / 80, j = i - c*80;
        float w;
        if (j < 16)      w = Wd[j*CC + c];
        else if (j < 64) w = Wc[(j-16)*CC + c];
        else             w = Wa[(j-64)*CC + c];
        sW[i] = w;
    }
    if (tid < 80) sB[tid] = (tid < 16) ? bd[tid] : (tid < 64 ? bc[tid-16] : 0.f);

    const float* xp = x + (size_t)n*CC*TVTOT + tv0;
    for (int i = tid; i < 2048; i += 320) {
        int c = i >> 5, o = (i & 31) << 2;
        *reinterpret_cast<float4*>(&sX[c*128 + o]) =
            *reinterpret_cast<const float4*>(xp + (size_t)c*TVTOT + o);
    }
    __syncthreads();

    int jt = tid / 32;             // 0..9 (8 channels each)
    int tq = (tid & 31) << 2;      // local tv, 4 wide
    ull acc2[8][2];
#pragma unroll
    for (int a = 0; a < 8; a++) { acc2[a][0] = 0ull; acc2[a][1] = 0ull; }

#pragma unroll 4
    for (int c = 0; c < 64; c++) {
        ulonglong2 xv = *reinterpret_cast<const ulonglong2*>(&sX[c*128 + tq]);
        float4 wa = *reinterpret_cast<const float4*>(&sW[c*80 + jt*8]);
        float4 wb = *reinterpret_cast<const float4*>(&sW[c*80 + jt*8 + 4]);
        ull pw[8];
        pw[0]=pk2(wa.x,wa.x); pw[1]=pk2(wa.y,wa.y); pw[2]=pk2(wa.z,wa.z); pw[3]=pk2(wa.w,wa.w);
        pw[4]=pk2(wb.x,wb.x); pw[5]=pk2(wb.y,wb.y); pw[6]=pk2(wb.z,wb.z); pw[7]=pk2(wb.w,wb.w);
#pragma unroll
        for (int jj = 0; jj < 8; jj++) {
            acc2[jj][0] = fma2(pw[jj], xv.x, acc2[jj][0]);
            acc2[jj][1] = fma2(pw[jj], xv.y, acc2[jj][1]);
        }
    }

    float acc[8][4];
#pragma unroll
    for (int jj = 0; jj < 8; jj++) {
        unpk2(acc2[jj][0], acc[jj][0], acc[jj][1]);
        unpk2(acc2[jj][1], acc[jj][2], acc[jj][3]);
    }

    int j0 = jt*8;
    if (j0 < 64) {
        float b[8];
#pragma unroll
        for (int jj = 0; jj < 8; jj++) b[jj] = sB[j0+jj];
        float* gl = g_L + ((size_t)n*TVTOT + tv0 + tq)*64 + j0;
#pragma unroll
        for (int t4 = 0; t4 < 4; t4++) {
            float4 r0 = make_float4(acc[0][t4]+b[0], acc[1][t4]+b[1],
                                    acc[2][t4]+b[2], acc[3][t4]+b[3]);
            float4 r1 = make_float4(acc[4][t4]+b[4], acc[5][t4]+b[5],
                                    acc[6][t4]+b[6], acc[7][t4]+b[7]);
            *reinterpret_cast<float4*>(gl + (size_t)t4*64)     = r0;
            *reinterpret_cast<float4*>(gl + (size_t)t4*64 + 4) = r1;
        }
    } else {
#pragma unroll
        for (int jj = 0; jj < 8; jj++) {
            int o = j0 - 64 + jj;
            float4 r = make_float4(acc[jj][0], acc[jj][1], acc[jj][2], acc[jj][3]);
            *reinterpret_cast<float4*>(g_B + (size_t)(n*C4V + o)*TVTOT + tv0 + tq) = r;
        }
    }
}

// ============================================================
// K2: Gram partials (unchanged)
// ============================================================
__global__ void k2_gram(const float* __restrict__ ba)
{
    __shared__ float tile[32][W3V + 1];
    int n  = blockIdx.y;
    int ks = blockIdx.x;
    int tid = threadIdx.x;
    int tw1 = tid / 15, tw2 = tid % 15;

    float acc[5][5];
#pragma unroll
    for (int i = 0; i < 5; i++)
#pragma unroll
        for (int j = 0; j < 5; j++) acc[i][j] = 0.f;

    int k0 = ks * KCHUNK;
    for (int kt = 0; kt < KCHUNK; kt += 32) {
        for (int i = tid; i < 32*W3V; i += blockDim.x) {
            int r = i / W3V, w = i - r*W3V;
            int k = k0 + kt + r;
            int o = k >> 9, t = k & 511;
            int win = w / VV, v = w - win*VV;
            int ts = t + win - 1;
            float val = ba[o];
            if (ts >= 0 && ts < TT)
                val += g_B[((size_t)(n*C4V + o)*TT + ts)*VV + v];
            tile[r][w] = val;
        }
        __syncthreads();
        if (tid < 225) {
#pragma unroll 4
            for (int r = 0; r < 32; r++) {
                float av[5], bv[5];
#pragma unroll
                for (int i = 0; i < 5; i++) { av[i] = tile[r][tw1*5+i]; bv[i] = tile[r][tw2*5+i]; }
#pragma unroll
                for (int i = 0; i < 5; i++)
#pragma unroll
                    for (int j = 0; j < 5; j++) acc[i][j] += av[i]*bv[j];
            }
        }
        __syncthreads();
    }
    if (tid < 225) {
        float* gp = g_Gpart + (size_t)(n*KSPLIT + ks)*W3V*W3V;
#pragma unroll
        for (int i = 0; i < 5; i++)
#pragma unroll
            for (int j = 0; j < 5; j++)
                gp[(tw1*5+i)*W3V + (tw2*5+j)] = acc[i][j];
    }
}

// ============================================================
// K3: reduce + softmax over w1 (unchanged)
// ============================================================
__global__ void k3_softmax()
{
    __shared__ float sG[W3V*W3V];
    int n = blockIdx.x, tid = threadIdx.x;
    for (int i = tid; i < W3V*W3V; i += blockDim.x) {
        float s = 0.f;
        for (int p = 0; p < KSPLIT; p++)
            s += g_Gpart[(size_t)(n*KSPLIT + p)*W3V*W3V + i];
        sG[i] = s * (1.0f / (float)W3V);
    }
    __syncthreads();
    if (tid < W3V) {
        float mx = -1e30f;
        for (int w1 = 0; w1 < W3V; w1++) mx = fmaxf(mx, sG[w1*W3V + tid]);
        float sum = 0.f;
        for (int w1 = 0; w1 < W3V; w1++) {
            float e = expf(sG[w1*W3V + tid] - mx);
            sG[w1*W3V + tid] = e;
            sum += e;
        }
        float inv = 1.f / sum;
        for (int w1 = 0; w1 < W3V; w1++)
            g_att[(size_t)n*W3V*W3V + w1*W3V + tid] = sG[w1*W3V + tid] * inv;
    }
}

// ============================================================
// K4 v5: identical to v4 but __launch_bounds__(512, 1) so the
// 40-register f32x2 accumulator tile fits WITHOUT local spills.
// ============================================================
#define SM_R    0       /* R chunk [75][80 stride] = 6000 */
#define SM_LTX  6000    /* LT [75][256] (19200) / X1 [256][75] union */
#define SM_WOT  25200   /* WoT [48][64] = 3072 */
#define SM_BN   28272   /* 128 */
#define SM_BIAS 28400   /* 64 */
#define SM_TOT  28464   /* floats = 113856 B */

__global__ void __launch_bounds__(512, 1) k4_main(
    const float* __restrict__ x,
    const float* __restrict__ A,   const float* __restrict__ PA,
    const float* __restrict__ bd,  const float* __restrict__ bc,
    const float* __restrict__ Wo,  const float* __restrict__ bo,
    const float* __restrict__ gma, const float* __restrict__ bta,
    const float* __restrict__ mean,const float* __restrict__ var,
    float* __restrict__ out)
{
    extern __shared__ float sm[];
    int tid = threadIdx.x;
    int n  = blockIdx.x >> 5;          // 32 blocks per n
    int t0 = (blockIdx.x & 31) << 4;   // 16 t per block

    // once-per-block constants
    for (int i = tid; i < 3072; i += 512) {
        int kc = i >> 6, o = i & 63;
        sm[SM_WOT + i] = Wo[o*48 + kc];
    }
    if (tid < 64) {
        float sc = gma[tid] * rsqrtf(var[tid] + 1e-5f);
        sm[SM_BN + tid]      = sc;
        sm[SM_BN + 64 + tid] = (bo[tid] - mean[tid])*sc + bta[tid];
        sm[SM_BIAS + tid]    = (tid < 16) ? bd[tid] : bc[tid-16];
    }

    // P3 tile mapping: warp-internal 8mt x 4nt for smem broadcast dedup
    int w = tid >> 5, l = tid & 31;
    int mt = ((w >> 1) << 3) + (l >> 2);   // 0..63
    int nt = ((w & 1) << 2) + (l & 3);     // 0..7
    int m0 = mt << 2;                      // 0..252
    int n0 = nt * 10;                      // 0..70

    ull acc[4][5];
#pragma unroll
    for (int a = 0; a < 4; a++)
#pragma unroll
        for (int j = 0; j < 5; j++) acc[a][j] = 0ull;

    const float* gl = g_L + (size_t)n*TVTOT*64;

    for (int kk = 0; kk < 4; kk++) {
        __syncthreads();   // constants ready (kk=0) / previous compute done
        // R chunk [75 k][stride 80]
        if (kk == 0) {
            const float* ap = g_att + (size_t)n*5625;
            for (int i = tid; i < 5625; i += 512) {
                int k = i / 75, c = i - k*75;
                sm[SM_R + k*80 + c] = ap[i];
            }
        } else {
            const float* a0 = A  + (size_t)(kk-1)*5625;
            const float* p0 = PA + (size_t)(kk-1)*5625;
            for (int i = tid; i < 5625; i += 512) {
                int k = i / 75, c = i - k*75;
                sm[SM_R + k*80 + c] = a0[i] + p0[i];
            }
        }
        // LT gather: LT[k][m=(it*16+c)]  (padding rows -> bias)
        for (int i = tid; i < 4800; i += 512) {
            int seg = i >> 2, q = (i & 3) << 2;
            int k  = seg >> 4, it = seg & 15;
            int win = (k*41) >> 10;   // k/25 for k<75
            int v   = k - win*25;
            int ts  = t0 + it + win - 1;
            float4 val;
            if ((unsigned)ts < TT)
                val = *reinterpret_cast<const float4*>(gl + ((size_t)(ts*25 + v) << 6) + kk*16 + q);
            else
                val = *reinterpret_cast<const float4*>(&sm[SM_BIAS + kk*16 + q]);
            *reinterpret_cast<float4*>(&sm[SM_LTX + k*256 + it*16 + q]) = val;
        }
        __syncthreads();

        // chunk GEMM: acc[4m][5 f32x2] += LT[k][m] * R[k][n-pair]
        const float* ltb = &sm[SM_LTX + m0];
#pragma unroll 5
        for (int k = 0; k < 75; k++) {
            float4 a4 = *reinterpret_cast<const float4*>(ltb + k*256);
            ull pa0 = pk2(a4.x, a4.x), pa1 = pk2(a4.y, a4.y);
            ull pa2 = pk2(a4.z, a4.z), pa3 = pk2(a4.w, a4.w);
            const ull* rp = reinterpret_cast<const ull*>(&sm[SM_R + k*80 + n0]);
#pragma unroll
            for (int j = 0; j < 5; j++) {
                ull r = rp[j];
                acc[0][j] = fma2(pa0, r, acc[0][j]);
                acc[1][j] = fma2(pa1, r, acc[1][j]);
                acc[2][j] = fma2(pa2, r, acc[2][j]);
                acc[3][j] = fma2(pa3, r, acc[3][j]);
            }
        }
    }
    __syncthreads();

    // X1 [m][75] overwrites LT region (n >= 75 lanes discarded)
#pragma unroll
    for (int mi = 0; mi < 4; mi++) {
        float* xb = &sm[SM_LTX + (m0 + mi)*75];
#pragma unroll
        for (int j = 0; j < 5; j++) {
            float lo, hi; unpk2(acc[mi][j], lo, hi);
            int nn = n0 + 2*j;
            if (nn < 75)     xb[nn]     = lo;
            if (nn + 1 < 75) xb[nn + 1] = hi;
        }
    }
    __syncthreads();

    // P4: out conv (1,3,1) + BN + residual + relu (two passes of 8 t)
    if (tid < 320) {
        int itb = tid / 40;
        int r   = tid - itb*40;
        int ot  = (r/5)*8, v0 = (r - (r/5)*5)*5;
#pragma unroll
        for (int pass = 0; pass < 2; pass++) {
            int it = itb + (pass << 3);
            float po[8][5];
#pragma unroll
            for (int a = 0; a < 8; a++)
#pragma unroll
                for (int b = 0; b < 5; b++) po[a][b] = 0.f;
            const float* x1b = &sm[SM_LTX + it*16*75];
#pragma unroll
            for (int c = 0; c < 16; c++) {
#pragma unroll
                for (int win = 0; win < 3; win++) {
                    int kc = c*3 + win;
                    float4 wA = *reinterpret_cast<const float4*>(&sm[SM_WOT + kc*64 + ot]);
                    float4 wB = *reinterpret_cast<const float4*>(&sm[SM_WOT + kc*64 + ot + 4]);
                    float wv[8] = {wA.x, wA.y, wA.z, wA.w, wB.x, wB.y, wB.z, wB.w};
                    float xv[5];
#pragma unroll
                    for (int i = 0; i < 5; i++) xv[i] = x1b[c*75 + win*25 + v0 + i];
#pragma unroll
                    for (int oo = 0; oo < 8; oo++)
#pragma unroll
                        for (int i = 0; i < 5; i++) po[oo][i] += wv[oo]*xv[i];
                }
            }
#pragma unroll
            for (int oo = 0; oo < 8; oo++) {
                int o = ot + oo;
                float sc = sm[SM_BN + o], sh = sm[SM_BN + 64 + o];
                size_t base = ((size_t)(n*COV + o)*TT + (t0 + it))*VV + v0;
#pragma unroll
                for (int i = 0; i < 5; i++)
                    out[base + i] = fmaxf(po[oo][i]*sc + sh + x[base + i], 0.f);
            }
        }
    }
}

// ============================================================
extern "C" void kernel_launch(void* const* d_in, const int* in_sizes, int n_in,
                              void* d_out, int out_size)
{
    (void)in_sizes; (void)n_in; (void)out_size;
    const float* x   = (const float*)d_in[0];
    const float* A   = (const float*)d_in[1];
    const float* PA  = (const float*)d_in[2];
    const float* Waw = (const float*)d_in[3];
    const float* Wab = (const float*)d_in[4];
    const float* Wdw = (const float*)d_in[5];
    const float* Wdb = (const float*)d_in[6];
    const float* Wcw = (const float*)d_in[7];
    const float* Wcb = (const float*)d_in[8];
    const float* Wow = (const float*)d_in[9];
    const float* Wob = (const float*)d_in[10];
    const float* gm  = (const float*)d_in[11];
    const float* bt  = (const float*)d_in[12];
    const float* mn  = (const float*)d_in[13];
    const float* vr  = (const float*)d_in[14];
    float* out = (float*)d_out;

    const size_t smem1 = (8192 + 5120 + 80) * sizeof(float);
    const size_t smem4 = SM_TOT * sizeof(float);
    cudaFuncSetAttribute(k1_conv80, cudaFuncAttributeMaxDynamicSharedMemorySize, (int)smem1);
    cudaFuncSetAttribute(k4_main,   cudaFuncAttributeMaxDynamicSharedMemorySize, (int)smem4);

    k1_conv80<<<dim3(TVTOT/K1_TV, NN), 320, smem1>>>(x, Waw, Wdw, Wdb, Wcw, Wcb);
    k2_gram  <<<dim3(KSPLIT, NN), 256>>>(Wab);
    k3_softmax<<<NN, 128>>>();
    k4_main  <<<NN*(TT/16), 512, smem4>>>(x, A, PA, Wdb, Wcb,
                                          Wow, Wob, gm, bt, mn, vr, out);
}

// round 6
// speedup vs baseline: 1.1523x; 1.0940x over previous
#include <cuda_runtime.h>
#include <math.h>
#include <stdint.h>

#define NN 32
#define CC 64
#define TT 512
#define VV 25
#define C4V 16
#define W3V 75
#define COV 64
#define KSPLIT 8
#define KTOT (C4V*TT)        /* 8192 */
#define KCHUNK (KTOT/KSPLIT) /* 1024 */
#define TVTOT (TT*VV)        /* 12800 */
#define TVPAD 12850          /* (512+2)*25, pad row at t=-1 and t=512 */

typedef unsigned long long ull;

__device__ __forceinline__ ull pk2(float lo, float hi) {
    ull r; asm("mov.b64 %0, {%1,%2};" : "=l"(r) : "f"(lo), "f"(hi)); return r;
}
__device__ __forceinline__ ull fma2(ull a, ull b, ull c) {
    ull d; asm("fma.rn.f32x2 %0, %1, %2, %3;" : "=l"(d) : "l"(a), "l"(b), "l"(c)); return d;
}
__device__ __forceinline__ void unpk2(ull v, float& lo, float& hi) {
    asm("mov.b64 {%0,%1}, %2;" : "=f"(lo), "=f"(hi) : "l"(v));
}
__device__ __forceinline__ void cpa16(uint32_t s, const void* g) {
    asm volatile("cp.async.cg.shared.global [%0], [%1], 16;" :: "r"(s), "l"(g));
}
__device__ __forceinline__ void cpa_commit() {
    asm volatile("cp.async.commit_group;" ::: "memory");
}
template<int N> __device__ __forceinline__ void cpa_wait() {
    asm volatile("cp.async.wait_group %0;" :: "n"(N) : "memory");
}

// -------- device scratch --------
__device__ float g_B[NN*C4V*TT*VV];              // conv_a(x), ch-major, NO bias
__device__ float g_L[(size_t)NN*TVPAD*64];       // [n][tvp][ch], bias-padded rows
__device__ float g_Gpart[NN*KSPLIT*W3V*W3V];
__device__ float g_attp[NN*W3V*80];              // att padded stride 80
__device__ float g_Aeff[3*W3V*80];               // A+PA padded stride 80

// ============================================================
// K0: fill Aeff (padded) + g_L bias pad rows
// ============================================================
__global__ void k0_init(const float* __restrict__ A, const float* __restrict__ PA,
                        const float* __restrict__ bd, const float* __restrict__ bc)
{
    int i = blockIdx.x*blockDim.x + threadIdx.x;
    if (i < 16875) {
        int k = i / 5625, r = i - k*5625;
        int w1 = r / 75, w2 = r - w1*75;
        g_Aeff[k*6000 + w1*80 + w2] = A[i] + PA[i];
    }
    if (i < 102400) {
        int ch = i & 63, rr = i >> 6;     // rr = n*50 + row
        int n = rr / 50, row = rr - n*50;
        int tvp = (row < 25) ? row : (TVPAD - 25 + row - 25);
        float b = (ch < 16) ? bd[ch] : bc[ch-16];
        g_L[((size_t)n*TVPAD + tvp)*64 + ch] = b;
    }
}

// ============================================================
// K1: 80-channel 1x1 conv GEMM on raw x
// ============================================================
#define K1_TV 128
__global__ void __launch_bounds__(320) k1_conv80(
    const float* __restrict__ x,
    const float* __restrict__ Wa,
    const float* __restrict__ Wd, const float* __restrict__ bd,
    const float* __restrict__ Wc, const float* __restrict__ bc)
{
    extern __shared__ float sm[];
    float* sX = sm;                 // [64][128]
    float* sW = sm + 8192;          // [64c][80j]
    float* sB = sm + 8192 + 5120;   // [80]
    int tid = threadIdx.x;
    int n   = blockIdx.y;
    int tv0 = blockIdx.x * K1_TV;

    for (int i = tid; i < 5120; i += 320) {
        int c = i / 80, j = i - c*80;
        float w;
        if (j < 16)      w = Wd[j*CC + c];
        else if (j < 64) w = Wc[(j-16)*CC + c];
        else             w = Wa[(j-64)*CC + c];
        sW[i] = w;
    }
    if (tid < 80) sB[tid] = (tid < 16) ? bd[tid] : (tid < 64 ? bc[tid-16] : 0.f);

    const float* xp = x + (size_t)n*CC*TVTOT + tv0;
    for (int i = tid; i < 2048; i += 320) {
        int c = i >> 5, o = (i & 31) << 2;
        *reinterpret_cast<float4*>(&sX[c*128 + o]) =
            *reinterpret_cast<const float4*>(xp + (size_t)c*TVTOT + o);
    }
    __syncthreads();

    int jt = tid / 32;
    int tq = (tid & 31) << 2;
    ull acc2[8][2];
#pragma unroll
    for (int a = 0; a < 8; a++) { acc2[a][0] = 0ull; acc2[a][1] = 0ull; }

#pragma unroll 4
    for (int c = 0; c < 64; c++) {
        ulonglong2 xv = *reinterpret_cast<const ulonglong2*>(&sX[c*128 + tq]);
        float4 wa = *reinterpret_cast<const float4*>(&sW[c*80 + jt*8]);
        float4 wb = *reinterpret_cast<const float4*>(&sW[c*80 + jt*8 + 4]);
        ull pw[8];
        pw[0]=pk2(wa.x,wa.x); pw[1]=pk2(wa.y,wa.y); pw[2]=pk2(wa.z,wa.z); pw[3]=pk2(wa.w,wa.w);
        pw[4]=pk2(wb.x,wb.x); pw[5]=pk2(wb.y,wb.y); pw[6]=pk2(wb.z,wb.z); pw[7]=pk2(wb.w,wb.w);
#pragma unroll
        for (int jj = 0; jj < 8; jj++) {
            acc2[jj][0] = fma2(pw[jj], xv.x, acc2[jj][0]);
            acc2[jj][1] = fma2(pw[jj], xv.y, acc2[jj][1]);
        }
    }

    float acc[8][4];
#pragma unroll
    for (int jj = 0; jj < 8; jj++) {
        unpk2(acc2[jj][0], acc[jj][0], acc[jj][1]);
        unpk2(acc2[jj][1], acc[jj][2], acc[jj][3]);
    }

    int j0 = jt*8;
    if (j0 < 64) {
        float b[8];
#pragma unroll
        for (int jj = 0; jj < 8; jj++) b[jj] = sB[j0+jj];
        float* gl = g_L + ((size_t)n*TVPAD + 25 + tv0 + tq)*64 + j0;
#pragma unroll
        for (int t4 = 0; t4 < 4; t4++) {
            float4 r0 = make_float4(acc[0][t4]+b[0], acc[1][t4]+b[1],
                                    acc[2][t4]+b[2], acc[3][t4]+b[3]);
            float4 r1 = make_float4(acc[4][t4]+b[4], acc[5][t4]+b[5],
                                    acc[6][t4]+b[6], acc[7][t4]+b[7]);
            *reinterpret_cast<float4*>(gl + (size_t)t4*64)     = r0;
            *reinterpret_cast<float4*>(gl + (size_t)t4*64 + 4) = r1;
        }
    } else {
#pragma unroll
        for (int jj = 0; jj < 8; jj++) {
            int o = j0 - 64 + jj;
            float4 r = make_float4(acc[jj][0], acc[jj][1], acc[jj][2], acc[jj][3]);
            *reinterpret_cast<float4*>(g_B + (size_t)(n*C4V + o)*TVTOT + tv0 + tq) = r;
        }
    }
}

// ============================================================
// K2: Gram partials (unchanged)
// ============================================================
__global__ void k2_gram(const float* __restrict__ ba)
{
    __shared__ float tile[32][W3V + 1];
    int n  = blockIdx.y;
    int ks = blockIdx.x;
    int tid = threadIdx.x;
    int tw1 = tid / 15, tw2 = tid % 15;

    float acc[5][5];
#pragma unroll
    for (int i = 0; i < 5; i++)
#pragma unroll
        for (int j = 0; j < 5; j++) acc[i][j] = 0.f;

    int k0 = ks * KCHUNK;
    for (int kt = 0; kt < KCHUNK; kt += 32) {
        for (int i = tid; i < 32*W3V; i += blockDim.x) {
            int r = i / W3V, w = i - r*W3V;
            int k = k0 + kt + r;
            int o = k >> 9, t = k & 511;
            int win = w / VV, v = w - win*VV;
            int ts = t + win - 1;
            float val = ba[o];
            if (ts >= 0 && ts < TT)
                val += g_B[((size_t)(n*C4V + o)*TT + ts)*VV + v];
            tile[r][w] = val;
        }
        __syncthreads();
        if (tid < 225) {
#pragma unroll 4
            for (int r = 0; r < 32; r++) {
                float av[5], bv[5];
#pragma unroll
                for (int i = 0; i < 5; i++) { av[i] = tile[r][tw1*5+i]; bv[i] = tile[r][tw2*5+i]; }
#pragma unroll
                for (int i = 0; i < 5; i++)
#pragma unroll
                    for (int j = 0; j < 5; j++) acc[i][j] += av[i]*bv[j];
            }
        }
        __syncthreads();
    }
    if (tid < 225) {
        float* gp = g_Gpart + (size_t)(n*KSPLIT + ks)*W3V*W3V;
#pragma unroll
        for (int i = 0; i < 5; i++)
#pragma unroll
            for (int j = 0; j < 5; j++)
                gp[(tw1*5+i)*W3V + (tw2*5+j)] = acc[i][j];
    }
}

// ============================================================
// K3: reduce + softmax over w1 -> padded att
// ============================================================
__global__ void k3_softmax()
{
    __shared__ float sG[W3V*W3V];
    int n = blockIdx.x, tid = threadIdx.x;
    for (int i = tid; i < W3V*W3V; i += blockDim.x) {
        float s = 0.f;
        for (int p = 0; p < KSPLIT; p++)
            s += g_Gpart[(size_t)(n*KSPLIT + p)*W3V*W3V + i];
        sG[i] = s * (1.0f / (float)W3V);
    }
    __syncthreads();
    if (tid < W3V) {
        float mx = -1e30f;
        for (int w1 = 0; w1 < W3V; w1++) mx = fmaxf(mx, sG[w1*W3V + tid]);
        float sum = 0.f;
        for (int w1 = 0; w1 < W3V; w1++) {
            float e = expf(sG[w1*W3V + tid] - mx);
            sG[w1*W3V + tid] = e;
            sum += e;
        }
        float inv = 1.f / sum;
        for (int w1 = 0; w1 < W3V; w1++)
            g_attp[(size_t)n*6000 + w1*80 + tid] = sG[w1*W3V + tid] * inv;
    }
}

// ============================================================
// K4 v6: cp.async double-buffered chunk pipeline.
// ============================================================
#define SM_R0   0       /* R buf0 [75][80] = 6000 */
#define SM_R1   6000    /* R buf1 */
#define SM_LT0  12000   /* LT buf0 [75][256] = 19200 ; X1 union after loop */
#define SM_LT1  31200   /* LT buf1 */
#define SM_WOT  50400   /* WoT [48][64] = 3072 */
#define SM_BN   53472   /* 128 */
#define SM_TOT  53600   /* floats = 214400 B */

__global__ void __launch_bounds__(512, 1) k4_main(
    const float* __restrict__ x,
    const float* __restrict__ Wo,  const float* __restrict__ bo,
    const float* __restrict__ gma, const float* __restrict__ bta,
    const float* __restrict__ mean,const float* __restrict__ var,
    float* __restrict__ out)
{
    extern __shared__ float sm[];
    uint32_t sbase = (uint32_t)__cvta_generic_to_shared(sm);
    int tid = threadIdx.x;
    int n  = blockIdx.x >> 5;          // 32 blocks per n
    int t0 = (blockIdx.x & 31) << 4;   // 16 t per block

    // once-per-block constants
    for (int i = tid; i < 3072; i += 512) {
        int kc = i >> 6, o = i & 63;
        sm[SM_WOT + i] = Wo[o*48 + kc];
    }
    if (tid < 64) {
        float sc = gma[tid] * rsqrtf(var[tid] + 1e-5f);
        sm[SM_BN + tid]      = sc;
        sm[SM_BN + 64 + tid] = (bo[tid] - mean[tid])*sc + bta[tid];
    }

    const float* gl = g_L + (size_t)n*TVPAD*64;

    // ---- async chunk issue ----
    auto issue_chunk = [&](int kk, int buf) {
        // R chunk: 1500 x 16B
        uint32_t rdst = sbase + (buf ? SM_R1 : SM_R0)*4;
        const float* rsrc = (kk == 0) ? (g_attp + (size_t)n*6000)
                                      : (g_Aeff + (size_t)(kk-1)*6000);
        for (int i = tid; i < 1500; i += 512)
            cpa16(rdst + i*16, rsrc + i*4);
        // LT chunk: 4800 x 16B, tvp = (t0+it+win)*25 + v (bias padding built-in)
        uint32_t ldst = sbase + (buf ? SM_LT1 : SM_LT0)*4;
        for (int i = tid; i < 4800; i += 512) {
            int seg = i >> 2, q = (i & 3) << 2;
            int k  = seg >> 4, it = seg & 15;
            int win = (k*41) >> 10;   // k/25 for k<75
            int v   = k - win*25;
            int tvp = (t0 + it + win)*25 + v;
            cpa16(ldst + (k*256 + it*16 + q)*4,
                  gl + ((size_t)tvp << 6) + kk*16 + q);
        }
    };

    // P3 tile mapping: warp-internal 8mt x 4nt
    int w = tid >> 5, l = tid & 31;
    int mt = ((w >> 1) << 3) + (l >> 2);   // 0..63
    int nt = ((w & 1) << 2) + (l & 3);     // 0..7
    int m0 = mt << 2;
    int n0 = nt * 10;

    ull acc[4][5];
#pragma unroll
    for (int a = 0; a < 4; a++)
#pragma unroll
        for (int j = 0; j < 5; j++) acc[a][j] = 0ull;

    issue_chunk(0, 0); cpa_commit();

    for (int kk = 0; kk < 4; kk++) {
        if (kk < 3) {
            issue_chunk(kk+1, (kk+1) & 1); cpa_commit();
            cpa_wait<1>();
        } else {
            cpa_wait<0>();
        }
        __syncthreads();

        const float* ltb = &sm[(kk & 1 ? SM_LT1 : SM_LT0) + m0];
        const float* rb  = &sm[(kk & 1 ? SM_R1  : SM_R0)];
#pragma unroll 5
        for (int k = 0; k < 75; k++) {
            float4 a4 = *reinterpret_cast<const float4*>(ltb + k*256);
            ull pa0 = pk2(a4.x, a4.x), pa1 = pk2(a4.y, a4.y);
            ull pa2 = pk2(a4.z, a4.z), pa3 = pk2(a4.w, a4.w);
            const ull* rp = reinterpret_cast<const ull*>(rb + k*80 + n0);
#pragma unroll
            for (int j = 0; j < 5; j++) {
                ull r = rp[j];
                acc[0][j] = fma2(pa0, r, acc[0][j]);
                acc[1][j] = fma2(pa1, r, acc[1][j]);
                acc[2][j] = fma2(pa2, r, acc[2][j]);
                acc[3][j] = fma2(pa3, r, acc[3][j]);
            }
        }
        __syncthreads();
    }

    // X1 [m][75] into SM_LT0 (buf0 dead: last GEMM used buf1)
#pragma unroll
    for (int mi = 0; mi < 4; mi++) {
        float* xb = &sm[SM_LT0 + (m0 + mi)*75];
#pragma unroll
        for (int j = 0; j < 5; j++) {
            float lo, hi; unpk2(acc[mi][j], lo, hi);
            int nn = n0 + 2*j;
            if (nn < 75)     xb[nn]     = lo;
            if (nn + 1 < 75) xb[nn + 1] = hi;
        }
    }
    __syncthreads();

    // P4: out conv (1,3,1) + BN + residual + relu
    if (tid < 320) {
        int itb = tid / 40;
        int r   = tid - itb*40;
        int ot  = (r/5)*8, v0 = (r - (r/5)*5)*5;
#pragma unroll
        for (int pass = 0; pass < 2; pass++) {
            int it = itb + (pass << 3);
            float po[8][5];
#pragma unroll
            for (int a = 0; a < 8; a++)
#pragma unroll
                for (int b = 0; b < 5; b++) po[a][b] = 0.f;
            const float* x1b = &sm[SM_LT0 + it*16*75];
#pragma unroll
            for (int c = 0; c < 16; c++) {
#pragma unroll
                for (int win = 0; win < 3; win++) {
                    int kc = c*3 + win;
                    float4 wA = *reinterpret_cast<const float4*>(&sm[SM_WOT + kc*64 + ot]);
                    float4 wB = *reinterpret_cast<const float4*>(&sm[SM_WOT + kc*64 + ot + 4]);
                    float wv[8] = {wA.x, wA.y, wA.z, wA.w, wB.x, wB.y, wB.z, wB.w};
                    float xv[5];
#pragma unroll
                    for (int i = 0; i < 5; i++) xv[i] = x1b[c*75 + win*25 + v0 + i];
#pragma unroll
                    for (int oo = 0; oo < 8; oo++)
#pragma unroll
                        for (int i = 0; i < 5; i++) po[oo][i] += wv[oo]*xv[i];
                }
            }
#pragma unroll
            for (int oo = 0; oo < 8; oo++) {
                int o = ot + oo;
                float sc = sm[SM_BN + o], sh = sm[SM_BN + 64 + o];
                size_t base = ((size_t)(n*COV + o)*TT + (t0 + it))*VV + v0;
#pragma unroll
                for (int i = 0; i < 5; i++)
                    out[base + i] = fmaxf(po[oo][i]*sc + sh + x[base + i], 0.f);
            }
        }
    }
}

// ============================================================
extern "C" void kernel_launch(void* const* d_in, const int* in_sizes, int n_in,
                              void* d_out, int out_size)
{
    (void)in_sizes; (void)n_in; (void)out_size;
    const float* x   = (const float*)d_in[0];
    const float* A   = (const float*)d_in[1];
    const float* PA  = (const float*)d_in[2];
    const float* Waw = (const float*)d_in[3];
    const float* Wab = (const float*)d_in[4];
    const float* Wdw = (const float*)d_in[5];
    const float* Wdb = (const float*)d_in[6];
    const float* Wcw = (const float*)d_in[7];
    const float* Wcb = (const float*)d_in[8];
    const float* Wow = (const float*)d_in[9];
    const float* Wob = (const float*)d_in[10];
    const float* gm  = (const float*)d_in[11];
    const float* bt  = (const float*)d_in[12];
    const float* mn  = (const float*)d_in[13];
    const float* vr  = (const float*)d_in[14];
    float* out = (float*)d_out;

    const size_t smem1 = (8192 + 5120 + 80) * sizeof(float);
    const size_t smem4 = SM_TOT * sizeof(float);
    cudaFuncSetAttribute(k1_conv80, cudaFuncAttributeMaxDynamicSharedMemorySize, (int)smem1);
    cudaFuncSetAttribute(k4_main,   cudaFuncAttributeMaxDynamicSharedMemorySize, (int)smem4);

    k0_init  <<<400, 256>>>(A, PA, Wdb, Wcb);
    k1_conv80<<<dim3(TVTOT/K1_TV, NN), 320, smem1>>>(x, Waw, Wdw, Wdb, Wcw, Wcb);
    k2_gram  <<<dim3(KSPLIT, NN), 256>>>(Wab);
    k3_softmax<<<NN, 128>>>();
    k4_main  <<<NN*(TT/16), 512, smem4>>>(x, Wow, Wob, gm, bt, mn, vr, out);
}

// round 7
// speedup vs baseline: 1.1605x; 1.0072x over previous
#include <cuda_runtime.h>
#include <math.h>
#include <stdint.h>

#define NN 32
#define CC 64
#define TT 512
#define VV 25
#define C4V 16
#define W3V 75
#define COV 64
#define KSPLIT 8
#define KTOT (C4V*TT)        /* 8192 */
#define KCHUNK (KTOT/KSPLIT) /* 1024 */
#define TVTOT (TT*VV)        /* 12800 */
#define TVPAD 12850          /* (512+2)*25, pad row at t=-1 and t=512 */

typedef unsigned long long ull;

__device__ __forceinline__ ull pk2(float lo, float hi) {
    ull r; asm("mov.b64 %0, {%1,%2};" : "=l"(r) : "f"(lo), "f"(hi)); return r;
}
__device__ __forceinline__ ull fma2(ull a, ull b, ull c) {
    ull d; asm("fma.rn.f32x2 %0, %1, %2, %3;" : "=l"(d) : "l"(a), "l"(b), "l"(c)); return d;
}
__device__ __forceinline__ void unpk2(ull v, float& lo, float& hi) {
    asm("mov.b64 {%0,%1}, %2;" : "=f"(lo), "=f"(hi) : "l"(v));
}
__device__ __forceinline__ void cpa16(uint32_t s, const void* g) {
    asm volatile("cp.async.cg.shared.global [%0], [%1], 16;" :: "r"(s), "l"(g));
}
__device__ __forceinline__ void cpa_commit() {
    asm volatile("cp.async.commit_group;" ::: "memory");
}
template<int N> __device__ __forceinline__ void cpa_wait() {
    asm volatile("cp.async.wait_group %0;" :: "n"(N) : "memory");
}

// -------- device scratch --------
__device__ float g_B[NN*C4V*TT*VV];              // conv_a(x), ch-major, NO bias
__device__ float g_L[(size_t)NN*TVPAD*64];       // [n][tvp][ch], bias-padded rows
__device__ float g_Gpart[NN*KSPLIT*W3V*W3V];
__device__ float g_attp[NN*W3V*80];              // att padded stride 80
__device__ float g_Aeff[3*W3V*80];               // A+PA padded stride 80

// ============================================================
// K0: fill Aeff (padded) + g_L bias pad rows
// ============================================================
__global__ void k0_init(const float* __restrict__ A, const float* __restrict__ PA,
                        const float* __restrict__ bd, const float* __restrict__ bc)
{
    int i = blockIdx.x*blockDim.x + threadIdx.x;
    if (i < 16875) {
        int k = i / 5625, r = i - k*5625;
        int w1 = r / 75, w2 = r - w1*75;
        g_Aeff[k*6000 + w1*80 + w2] = A[i] + PA[i];
    }
    if (i < 102400) {
        int ch = i & 63, rr = i >> 6;     // rr = n*50 + row
        int n = rr / 50, row = rr - n*50;
        int tvp = (row < 25) ? row : (TVPAD - 25 + row - 25);
        float b = (ch < 16) ? bd[ch] : bc[ch-16];
        g_L[((size_t)n*TVPAD + tvp)*64 + ch] = b;
    }
}

// ============================================================
// K1: 80-channel 1x1 conv GEMM on raw x
// ============================================================
#define K1_TV 128
__global__ void __launch_bounds__(320) k1_conv80(
    const float* __restrict__ x,
    const float* __restrict__ Wa,
    const float* __restrict__ Wd, const float* __restrict__ bd,
    const float* __restrict__ Wc, const float* __restrict__ bc)
{
    extern __shared__ float sm[];
    float* sX = sm;                 // [64][128]
    float* sW = sm + 8192;          // [64c][80j]
    float* sB = sm + 8192 + 5120;   // [80]
    int tid = threadIdx.x;
    int n   = blockIdx.y;
    int tv0 = blockIdx.x * K1_TV;

    for (int i = tid; i < 5120; i += 320) {
        int c = i / 80, j = i - c*80;
        float w;
        if (j < 16)      w = Wd[j*CC + c];
        else if (j < 64) w = Wc[(j-16)*CC + c];
        else             w = Wa[(j-64)*CC + c];
        sW[i] = w;
    }
    if (tid < 80) sB[tid] = (tid < 16) ? bd[tid] : (tid < 64 ? bc[tid-16] : 0.f);

    const float* xp = x + (size_t)n*CC*TVTOT + tv0;
    for (int i = tid; i < 2048; i += 320) {
        int c = i >> 5, o = (i & 31) << 2;
        *reinterpret_cast<float4*>(&sX[c*128 + o]) =
            *reinterpret_cast<const float4*>(xp + (size_t)c*TVTOT + o);
    }
    __syncthreads();

    int jt = tid / 32;
    int tq = (tid & 31) << 2;
    ull acc2[8][2];
#pragma unroll
    for (int a = 0; a < 8; a++) { acc2[a][0] = 0ull; acc2[a][1] = 0ull; }

#pragma unroll 4
    for (int c = 0; c < 64; c++) {
        ulonglong2 xv = *reinterpret_cast<const ulonglong2*>(&sX[c*128 + tq]);
        float4 wa = *reinterpret_cast<const float4*>(&sW[c*80 + jt*8]);
        float4 wb = *reinterpret_cast<const float4*>(&sW[c*80 + jt*8 + 4]);
        ull pw[8];
        pw[0]=pk2(wa.x,wa.x); pw[1]=pk2(wa.y,wa.y); pw[2]=pk2(wa.z,wa.z); pw[3]=pk2(wa.w,wa.w);
        pw[4]=pk2(wb.x,wb.x); pw[5]=pk2(wb.y,wb.y); pw[6]=pk2(wb.z,wb.z); pw[7]=pk2(wb.w,wb.w);
#pragma unroll
        for (int jj = 0; jj < 8; jj++) {
            acc2[jj][0] = fma2(pw[jj], xv.x, acc2[jj][0]);
            acc2[jj][1] = fma2(pw[jj], xv.y, acc2[jj][1]);
        }
    }

    float acc[8][4];
#pragma unroll
    for (int jj = 0; jj < 8; jj++) {
        unpk2(acc2[jj][0], acc[jj][0], acc[jj][1]);
        unpk2(acc2[jj][1], acc[jj][2], acc[jj][3]);
    }

    int j0 = jt*8;
    if (j0 < 64) {
        float b[8];
#pragma unroll
        for (int jj = 0; jj < 8; jj++) b[jj] = sB[j0+jj];
        float* gl = g_L + ((size_t)n*TVPAD + 25 + tv0 + tq)*64 + j0;
#pragma unroll
        for (int t4 = 0; t4 < 4; t4++) {
            float4 r0 = make_float4(acc[0][t4]+b[0], acc[1][t4]+b[1],
                                    acc[2][t4]+b[2], acc[3][t4]+b[3]);
            float4 r1 = make_float4(acc[4][t4]+b[4], acc[5][t4]+b[5],
                                    acc[6][t4]+b[6], acc[7][t4]+b[7]);
            *reinterpret_cast<float4*>(gl + (size_t)t4*64)     = r0;
            *reinterpret_cast<float4*>(gl + (size_t)t4*64 + 4) = r1;
        }
    } else {
#pragma unroll
        for (int jj = 0; jj < 8; jj++) {
            int o = j0 - 64 + jj;
            float4 r = make_float4(acc[jj][0], acc[jj][1], acc[jj][2], acc[jj][3]);
            *reinterpret_cast<float4*>(g_B + (size_t)(n*C4V + o)*TVTOT + tv0 + tq) = r;
        }
    }
}

// ============================================================
// K2: Gram partials (unchanged)
// ============================================================
__global__ void k2_gram(const float* __restrict__ ba)
{
    __shared__ float tile[32][W3V + 1];
    int n  = blockIdx.y;
    int ks = blockIdx.x;
    int tid = threadIdx.x;
    int tw1 = tid / 15, tw2 = tid % 15;

    float acc[5][5];
#pragma unroll
    for (int i = 0; i < 5; i++)
#pragma unroll
        for (int j = 0; j < 5; j++) acc[i][j] = 0.f;

    int k0 = ks * KCHUNK;
    for (int kt = 0; kt < KCHUNK; kt += 32) {
        for (int i = tid; i < 32*W3V; i += blockDim.x) {
            int r = i / W3V, w = i - r*W3V;
            int k = k0 + kt + r;
            int o = k >> 9, t = k & 511;
            int win = w / VV, v = w - win*VV;
            int ts = t + win - 1;
            float val = ba[o];
            if (ts >= 0 && ts < TT)
                val += g_B[((size_t)(n*C4V + o)*TT + ts)*VV + v];
            tile[r][w] = val;
        }
        __syncthreads();
        if (tid < 225) {
#pragma unroll 4
            for (int r = 0; r < 32; r++) {
                float av[5], bv[5];
#pragma unroll
                for (int i = 0; i < 5; i++) { av[i] = tile[r][tw1*5+i]; bv[i] = tile[r][tw2*5+i]; }
#pragma unroll
                for (int i = 0; i < 5; i++)
#pragma unroll
                    for (int j = 0; j < 5; j++) acc[i][j] += av[i]*bv[j];
            }
        }
        __syncthreads();
    }
    if (tid < 225) {
        float* gp = g_Gpart + (size_t)(n*KSPLIT + ks)*W3V*W3V;
#pragma unroll
        for (int i = 0; i < 5; i++)
#pragma unroll
            for (int j = 0; j < 5; j++)
                gp[(tw1*5+i)*W3V + (tw2*5+j)] = acc[i][j];
    }
}

// ============================================================
// K3: reduce + softmax over w1 -> padded att
// ============================================================
__global__ void k3_softmax()
{
    __shared__ float sG[W3V*W3V];
    int n = blockIdx.x, tid = threadIdx.x;
    for (int i = tid; i < W3V*W3V; i += blockDim.x) {
        float s = 0.f;
        for (int p = 0; p < KSPLIT; p++)
            s += g_Gpart[(size_t)(n*KSPLIT + p)*W3V*W3V + i];
        sG[i] = s * (1.0f / (float)W3V);
    }
    __syncthreads();
    if (tid < W3V) {
        float mx = -1e30f;
        for (int w1 = 0; w1 < W3V; w1++) mx = fmaxf(mx, sG[w1*W3V + tid]);
        float sum = 0.f;
        for (int w1 = 0; w1 < W3V; w1++) {
            float e = expf(sG[w1*W3V + tid] - mx);
            sG[w1*W3V + tid] = e;
            sum += e;
        }
        float inv = 1.f / sum;
        for (int w1 = 0; w1 < W3V; w1++)
            g_attp[(size_t)n*6000 + w1*80 + tid] = sG[w1*W3V + tid] * inv;
    }
}

// ============================================================
// K4 v6: cp.async double-buffered chunk pipeline.
// ============================================================
#define SM_R0   0       /* R buf0 [75][80] = 6000 */
#define SM_R1   6000    /* R buf1 */
#define SM_LT0  12000   /* LT buf0 [75][256] = 19200 ; X1 union after loop */
#define SM_LT1  31200   /* LT buf1 */
#define SM_WOT  50400   /* WoT [48][64] = 3072 */
#define SM_BN   53472   /* 128 */
#define SM_TOT  53600   /* floats = 214400 B */

__global__ void __launch_bounds__(512, 1) k4_main(
    const float* __restrict__ x,
    const float* __restrict__ Wo,  const float* __restrict__ bo,
    const float* __restrict__ gma, const float* __restrict__ bta,
    const float* __restrict__ mean,const float* __restrict__ var,
    float* __restrict__ out)
{
    extern __shared__ float sm[];
    uint32_t sbase = (uint32_t)__cvta_generic_to_shared(sm);
    int tid = threadIdx.x;
    int n  = blockIdx.x >> 5;          // 32 blocks per n
    int t0 = (blockIdx.x & 31) << 4;   // 16 t per block

    // once-per-block constants
    for (int i = tid; i < 3072; i += 512) {
        int kc = i >> 6, o = i & 63;
        sm[SM_WOT + i] = Wo[o*48 + kc];
    }
    if (tid < 64) {
        float sc = gma[tid] * rsqrtf(var[tid] + 1e-5f);
        sm[SM_BN + tid]      = sc;
        sm[SM_BN + 64 + tid] = (bo[tid] - mean[tid])*sc + bta[tid];
    }

    const float* gl = g_L + (size_t)n*TVPAD*64;

    // ---- async chunk issue ----
    auto issue_chunk = [&](int kk, int buf) {
        // R chunk: 1500 x 16B
        uint32_t rdst = sbase + (buf ? SM_R1 : SM_R0)*4;
        const float* rsrc = (kk == 0) ? (g_attp + (size_t)n*6000)
                                      : (g_Aeff + (size_t)(kk-1)*6000);
        for (int i = tid; i < 1500; i += 512)
            cpa16(rdst + i*16, rsrc + i*4);
        // LT chunk: 4800 x 16B, tvp = (t0+it+win)*25 + v (bias padding built-in)
        uint32_t ldst = sbase + (buf ? SM_LT1 : SM_LT0)*4;
        for (int i = tid; i < 4800; i += 512) {
            int seg = i >> 2, q = (i & 3) << 2;
            int k  = seg >> 4, it = seg & 15;
            int win = (k*41) >> 10;   // k/25 for k<75
            int v   = k - win*25;
            int tvp = (t0 + it + win)*25 + v;
            cpa16(ldst + (k*256 + it*16 + q)*4,
                  gl + ((size_t)tvp << 6) + kk*16 + q);
        }
    };

    // P3 tile mapping: warp-internal 8mt x 4nt
    int w = tid >> 5, l = tid & 31;
    int mt = ((w >> 1) << 3) + (l >> 2);   // 0..63
    int nt = ((w & 1) << 2) + (l & 3);     // 0..7
    int m0 = mt << 2;
    int n0 = nt * 10;

    ull acc[4][5];
#pragma unroll
    for (int a = 0; a < 4; a++)
#pragma unroll
        for (int j = 0; j < 5; j++) acc[a][j] = 0ull;

    issue_chunk(0, 0); cpa_commit();

    for (int kk = 0; kk < 4; kk++) {
        if (kk < 3) {
            issue_chunk(kk+1, (kk+1) & 1); cpa_commit();
            cpa_wait<1>();
        } else {
            cpa_wait<0>();
        }
        __syncthreads();

        const float* ltb = &sm[(kk & 1 ? SM_LT1 : SM_LT0) + m0];
        const float* rb  = &sm[(kk & 1 ? SM_R1  : SM_R0)];
#pragma unroll 5
        for (int k = 0; k < 75; k++) {
            float4 a4 = *reinterpret_cast<const float4*>(ltb + k*256);
            ull pa0 = pk2(a4.x, a4.x), pa1 = pk2(a4.y, a4.y);
            ull pa2 = pk2(a4.z, a4.z), pa3 = pk2(a4.w, a4.w);
            const ull* rp = reinterpret_cast<const ull*>(rb + k*80 + n0);
#pragma unroll
            for (int j = 0; j < 5; j++) {
                ull r = rp[j];
                acc[0][j] = fma2(pa0, r, acc[0][j]);
                acc[1][j] = fma2(pa1, r, acc[1][j]);
                acc[2][j] = fma2(pa2, r, acc[2][j]);
                acc[3][j] = fma2(pa3, r, acc[3][j]);
            }
        }
        __syncthreads();
    }

    // X1 [m][75] into SM_LT0 (buf0 dead: last GEMM used buf1)
#pragma unroll
    for (int mi = 0; mi < 4; mi++) {
        float* xb = &sm[SM_LT0 + (m0 + mi)*75];
#pragma unroll
        for (int j = 0; j < 5; j++) {
            float lo, hi; unpk2(acc[mi][j], lo, hi);
            int nn = n0 + 2*j;
            if (nn < 75)     xb[nn]     = lo;
            if (nn + 1 < 75) xb[nn + 1] = hi;
        }
    }
    __syncthreads();

    // P4: out conv (1,3,1) + BN + residual + relu
    if (tid < 320) {
        int itb = tid / 40;
        int r   = tid - itb*40;
        int ot  = (r/5)*8, v0 = (r - (r/5)*5)*5;
#pragma unroll
        for (int pass = 0; pass < 2; pass++) {
            int it = itb + (pass << 3);
            float po[8][5];
#pragma unroll
            for (int a = 0; a < 8; a++)
#pragma unroll
                for (int b = 0; b < 5; b++) po[a][b] = 0.f;
            const float* x1b = &sm[SM_LT0 + it*16*75];
#pragma unroll
            for (int c = 0; c < 16; c++) {
#pragma unroll
                for (int win = 0; win < 3; win++) {
                    int kc = c*3 + win;
                    float4 wA = *reinterpret_cast<const float4*>(&sm[SM_WOT + kc*64 + ot]);
                    float4 wB = *reinterpret_cast<const float4*>(&sm[SM_WOT + kc*64 + ot + 4]);
                    float wv[8] = {wA.x, wA.y, wA.z, wA.w, wB.x, wB.y, wB.z, wB.w};
                    float xv[5];
#pragma unroll
                    for (int i = 0; i < 5; i++) xv[i] = x1b[c*75 + win*25 + v0 + i];
#pragma unroll
                    for (int oo = 0; oo < 8; oo++)
#pragma unroll
                        for (int i = 0; i < 5; i++) po[oo][i] += wv[oo]*xv[i];
                }
            }
#pragma unroll
            for (int oo = 0; oo < 8; oo++) {
                int o = ot + oo;
                float sc = sm[SM_BN + o], sh = sm[SM_BN + 64 + o];
                size_t base = ((size_t)(n*COV + o)*TT + (t0 + it))*VV + v0;
#pragma unroll
                for (int i = 0; i < 5; i++)
                    out[base + i] = fmaxf(po[oo][i]*sc + sh + x[base + i], 0.f);
            }
        }
    }
}

// ============================================================
extern "C" void kernel_launch(void* const* d_in, const int* in_sizes, int n_in,
                              void* d_out, int out_size)
{
    (void)in_sizes; (void)n_in; (void)out_size;
    const float* x   = (const float*)d_in[0];
    const float* A   = (const float*)d_in[1];
    const float* PA  = (const float*)d_in[2];
    const float* Waw = (const float*)d_in[3];
    const float* Wab = (const float*)d_in[4];
    const float* Wdw = (const float*)d_in[5];
    const float* Wdb = (const float*)d_in[6];
    const float* Wcw = (const float*)d_in[7];
    const float* Wcb = (const float*)d_in[8];
    const float* Wow = (const float*)d_in[9];
    const float* Wob = (const float*)d_in[10];
    const float* gm  = (const float*)d_in[11];
    const float* bt  = (const float*)d_in[12];
    const float* mn  = (const float*)d_in[13];
    const float* vr  = (const float*)d_in[14];
    float* out = (float*)d_out;

    const size_t smem1 = (8192 + 5120 + 80) * sizeof(float);
    const size_t smem4 = SM_TOT * sizeof(float);
    cudaFuncSetAttribute(k1_conv80, cudaFuncAttributeMaxDynamicSharedMemorySize, (int)smem1);
    cudaFuncSetAttribute(k4_main,   cudaFuncAttributeMaxDynamicSharedMemorySize, (int)smem4);

    k0_init  <<<400, 256>>>(A, PA, Wdb, Wcb);
    k1_conv80<<<dim3(TVTOT/K1_TV, NN), 320, smem1>>>(x, Waw, Wdw, Wdb, Wcw, Wcb);
    k2_gram  <<<dim3(KSPLIT, NN), 256>>>(Wab);
    k3_softmax<<<NN, 128>>>();
    k4_main  <<<NN*(TT/16), 512, smem4>>>(x, Wow, Wob, gm, bt, mn, vr, out);
}